// round 16
// baseline (speedup 1.0000x reference)
#include <cuda_runtime.h>
#include <cuda_fp16.h>

#define NN 100000
#define EE 1600000
#define GG 256
#define NBLK 98   // ceil(NN/1024) for scan
#define SPLIT 50048  // node split for rgcn1/xw2 pipeline (multiple of 64 and 8)

// ---------------- scratch (__device__ globals, allocation-free) ----------------
__device__ __half g_hh[NN * 128];     // GAT transformed features (fp16)
__device__ float g_asrc[NN * 4];
__device__ float g_adst[NN * 4];
__device__ float g_w1[64 * 288];      // packed [k][r*32+c | root 256..287]
__device__ float g_w2[32 * 144];      // packed [k][r*16+c | root 128..143]
__device__ __half g_xw1[NN * 288];    // fp16
__device__ float g_z1[NN * 32];
__device__ __half g_xw2[NN * 144];    // fp16
__device__ float g_gmax[GG * 16];
__device__ float g_gsum[GG * 16];
__device__ float g_npg[GG];
// CSR
__device__ int g_deg[NN];
__device__ int g_off[NN];
__device__ int g_cur[NN];
__device__ int g_scan[NBLK * 1024];
__device__ int g_bsum[NBLK];
__device__ int g_bpre[NBLK];
__device__ int g_csr[EE];             // src | (rel<<20)

// ---------------- persistent streams/events (host-side objects only) ----------------
struct ForkCtx {
    cudaStream_t s2, s3;
    cudaEvent_t evStart, evCSR, evR1, evX2lo, evGat, evPack;
    ForkCtx() {
        cudaStreamCreateWithFlags(&s2, cudaStreamNonBlocking);
        cudaStreamCreateWithFlags(&s3, cudaStreamNonBlocking);
        cudaEventCreateWithFlags(&evStart, cudaEventDisableTiming);
        cudaEventCreateWithFlags(&evCSR, cudaEventDisableTiming);
        cudaEventCreateWithFlags(&evR1, cudaEventDisableTiming);
        cudaEventCreateWithFlags(&evX2lo, cudaEventDisableTiming);
        cudaEventCreateWithFlags(&evGat, cudaEventDisableTiming);
        cudaEventCreateWithFlags(&evPack, cudaEventDisableTiming);
    }
};
static ForkCtx g_fork;

// ---------------- helpers ----------------
__device__ __forceinline__ float lrelu(float x, float s) {
    return x > 0.f ? x : x * s;
}

__device__ __forceinline__ void atomicMaxF(float* addr, float v) {
    if (v >= 0.f) atomicMax((int*)addr, __float_as_int(v));
    else          atomicMin((unsigned int*)addr, __float_as_uint(v));
}

// packed dual-fp32 FMA (sm_100+): d = a * b + d, two lanes, exact fp32
__device__ __forceinline__ unsigned long long pk2(float lo, float hi) {
    unsigned long long r;
    asm("mov.b64 %0, {%1, %2};" : "=l"(r) : "f"(lo), "f"(hi));
    return r;
}
__device__ __forceinline__ void fma2(unsigned long long& d, unsigned long long a,
                                     unsigned long long b) {
    asm("fma.rn.f32x2 %0, %1, %2, %0;" : "+l"(d) : "l"(a), "l"(b));
}
__device__ __forceinline__ float2 upk2(unsigned long long v) {
    float lo, hi;
    asm("mov.b64 {%0, %1}, %2;" : "=f"(lo), "=f"(hi) : "l"(v));
    return make_float2(lo, hi);
}

// ---------------- init ----------------
__global__ void k_init() {
    int i = blockIdx.x * 256 + threadIdx.x;
    const float NEG_INF = __int_as_float(0xff800000);
    if (i < NN) g_deg[i] = 0;
    if (i < GG * 16) { g_gsum[i] = 0.f; g_gmax[i] = NEG_INF; }
    if (i < GG) g_npg[i] = 0.f;
}

// ---------------- pack relation weights ----------------
__global__ void k_pack(const float* __restrict__ rw1, const float* __restrict__ root1,
                       const float* __restrict__ rw2, const float* __restrict__ root2) {
    int i = blockIdx.x * 256 + threadIdx.x;
    if (i < 64 * 288) {
        int k = i / 288, j = i % 288;
        g_w1[i] = (j < 256) ? rw1[((j >> 5) * 64 + k) * 32 + (j & 31)]
                            : root1[k * 32 + (j - 256)];
    } else if (i < 64 * 288 + 32 * 144) {
        int t = i - 64 * 288;
        int k = t / 144, j = t % 144;
        g_w2[t] = (j < 128) ? rw2[((j >> 4) * 32 + k) * 16 + (j & 15)]
                            : root2[k * 16 + (j - 128)];
    }
}

// ---------------- CSR build ----------------
__global__ void k_count(const int* __restrict__ dst) {
    int e = blockIdx.x * 256 + threadIdx.x;
    atomicAdd(&g_deg[dst[e]], 1);
}

__global__ void k_scan1() {
    __shared__ int s[1024];
    int t = threadIdx.x;
    int i = blockIdx.x * 1024 + t;
    int v = (i < NN) ? g_deg[i] : 0;
    s[t] = v;
    __syncthreads();
    for (int ofs = 1; ofs < 1024; ofs <<= 1) {
        int add = (t >= ofs) ? s[t - ofs] : 0;
        __syncthreads();
        s[t] += add;
        __syncthreads();
    }
    g_scan[i] = s[t];
    if (t == 1023) g_bsum[blockIdx.x] = s[1023];
}

__global__ void k_scan2() {
    __shared__ int s[128];
    int t = threadIdx.x;
    int v = (t < NBLK) ? g_bsum[t] : 0;
    s[t] = v;
    __syncthreads();
    for (int ofs = 1; ofs < 128; ofs <<= 1) {
        int add = (t >= ofs) ? s[t - ofs] : 0;
        __syncthreads();
        s[t] += add;
        __syncthreads();
    }
    if (t < NBLK) g_bpre[t] = s[t] - v;  // exclusive
}

__global__ void k_scan3() {
    int i = blockIdx.x * 1024 + threadIdx.x;
    if (i < NN) {
        int excl = g_scan[i] - g_deg[i] + g_bpre[blockIdx.x];
        g_off[i] = excl;
        g_cur[i] = excl;
    }
}

__global__ void k_scatter(const int* __restrict__ src, const int* __restrict__ dst,
                          const int* __restrict__ et) {
    int e = blockIdx.x * 256 + threadIdx.x;
    int d = dst[e];
    int p = atomicAdd(&g_cur[d], 1);
    g_csr[p] = src[e] | (et[e] << 20);
}

// ---------------- SIMT smem GEMM with f32x2 FMA: C[N, OC_TOTAL] = A[N, IC] @ W[IC, OC_TOTAL], fp16 out ----------------
template<int IC, int OC_TOTAL, int OC_CHUNK, int NPB, int TN, int TC>
__global__ void __launch_bounds__((NPB / TN) * (OC_CHUNK / TC))
k_gemm(const float* __restrict__ A, const float* __restrict__ W, __half* __restrict__ C,
       int nbase) {
    constexpr int THREADS = (NPB / TN) * (OC_CHUNK / TC);
    __shared__ float ws[IC * OC_CHUNK];
    __shared__ float xs[NPB * IC];
    const int col0 = blockIdx.y * OC_CHUNK;

    for (int i = threadIdx.x; i < IC * OC_CHUNK / 4; i += THREADS) {
        int k = (i * 4) / OC_CHUNK, j = (i * 4) % OC_CHUNK;
        *(float4*)&ws[i * 4] = *(const float4*)&W[k * OC_TOTAL + col0 + j];
    }
    const int n0 = nbase + blockIdx.x * NPB;
    for (int i = threadIdx.x; i < NPB * IC / 4; i += THREADS) {
        int r = (i * 4) / IC, k = (i * 4) % IC;
        int n = n0 + r;
        float4 v = make_float4(0.f, 0.f, 0.f, 0.f);
        if (n < NN) v = *(const float4*)&A[n * IC + k];
        *(float4*)&xs[i * 4] = v;
    }
    __syncthreads();

    const int tc = threadIdx.x % (OC_CHUNK / TC);
    const int tn = threadIdx.x / (OC_CHUNK / TC);
    unsigned long long acc2[TN][TC / 2];
#pragma unroll
    for (int i = 0; i < TN; i++)
#pragma unroll
        for (int j2 = 0; j2 < TC / 2; j2++) acc2[i][j2] = 0ULL;

    const float* xb = &xs[tn * TN * IC];
    const float* wb = &ws[tc * TC];
    for (int k4 = 0; k4 < IC / 4; k4++) {
        float4 xv[TN];
#pragma unroll
        for (int i = 0; i < TN; i++) xv[i] = *(const float4*)&xb[i * IC + k4 * 4];
#pragma unroll
        for (int kk = 0; kk < 4; kk++) {
            unsigned long long wp[TC / 2];
#pragma unroll
            for (int j2 = 0; j2 < TC / 2; j2++)
                wp[j2] = *(const unsigned long long*)&wb[(k4 * 4 + kk) * OC_CHUNK + j2 * 2];
#pragma unroll
            for (int i = 0; i < TN; i++) {
                float xvk = (kk == 0) ? xv[i].x : (kk == 1) ? xv[i].y : (kk == 2) ? xv[i].z : xv[i].w;
                unsigned long long xd = pk2(xvk, xvk);
#pragma unroll
                for (int j2 = 0; j2 < TC / 2; j2++) fma2(acc2[i][j2], xd, wp[j2]);
            }
        }
    }
#pragma unroll
    for (int i = 0; i < TN; i++) {
        int n = n0 + tn * TN + i;
        if (n < NN) {
#pragma unroll
            for (int j4 = 0; j4 < TC / 4; j4++) {
                float2 p0 = upk2(acc2[i][j4 * 2]);
                float2 p1 = upk2(acc2[i][j4 * 2 + 1]);
                __half2 h0 = __floats2half2_rn(p0.x, p0.y);
                __half2 h1 = __floats2half2_rn(p1.x, p1.y);
                uint2 u;
                u.x = *(unsigned*)&h0;
                u.y = *(unsigned*)&h1;
                *(uint2*)&C[n * OC_TOTAL + col0 + tc * TC + j4 * 4] = u;
            }
        }
    }
}

// ---------------- GAT transform GEMM (f32x2) with fused attention-dot epilogue (fp16 h out) ----------------
__global__ void __launch_bounds__(96)
k_gemm_h(const float* __restrict__ A, const float* __restrict__ W,
         const float* __restrict__ att_src, const float* __restrict__ att_dst) {
    constexpr int IC = 64, OC = 128, NPB = 48, TN = 8, TC = 8, THREADS = 96;
    __shared__ float ws[IC * OC];
    __shared__ float xs[NPB * IC];

    for (int i = threadIdx.x; i < IC * OC / 4; i += THREADS)
        *(float4*)&ws[i * 4] = *(const float4*)&W[i * 4];
    const int n0 = blockIdx.x * NPB;
    for (int i = threadIdx.x; i < NPB * IC / 4; i += THREADS) {
        int r = (i * 4) / IC, k = (i * 4) % IC;
        int n = n0 + r;
        float4 v = make_float4(0.f, 0.f, 0.f, 0.f);
        if (n < NN) v = *(const float4*)&A[n * IC + k];
        *(float4*)&xs[i * 4] = v;
    }
    __syncthreads();

    const int tc = threadIdx.x % 16;
    const int tn = threadIdx.x / 16;
    unsigned long long acc2[TN][TC / 2];
#pragma unroll
    for (int i = 0; i < TN; i++)
#pragma unroll
        for (int j2 = 0; j2 < TC / 2; j2++) acc2[i][j2] = 0ULL;

    const float* xb = &xs[tn * TN * IC];
    const float* wb = &ws[tc * TC];
    for (int k4 = 0; k4 < IC / 4; k4++) {
        float4 xv[TN];
#pragma unroll
        for (int i = 0; i < TN; i++) xv[i] = *(const float4*)&xb[i * IC + k4 * 4];
#pragma unroll
        for (int kk = 0; kk < 4; kk++) {
            unsigned long long wp[TC / 2];
#pragma unroll
            for (int j2 = 0; j2 < TC / 2; j2++)
                wp[j2] = *(const unsigned long long*)&wb[(k4 * 4 + kk) * OC + j2 * 2];
#pragma unroll
            for (int i = 0; i < TN; i++) {
                float xvk = (kk == 0) ? xv[i].x : (kk == 1) ? xv[i].y : (kk == 2) ? xv[i].z : xv[i].w;
                unsigned long long xd = pk2(xvk, xvk);
#pragma unroll
                for (int j2 = 0; j2 < TC / 2; j2++) fma2(acc2[i][j2], xd, wp[j2]);
            }
        }
    }
    // unpack accumulators
    float acc[TN][TC];
#pragma unroll
    for (int i = 0; i < TN; i++)
#pragma unroll
        for (int j2 = 0; j2 < TC / 2; j2++) {
            float2 p = upk2(acc2[i][j2]);
            acc[i][j2 * 2] = p.x;
            acc[i][j2 * 2 + 1] = p.y;
        }
    // store h as fp16 (8 cols = 4 half2 = one uint4)
#pragma unroll
    for (int i = 0; i < TN; i++) {
        int n = n0 + tn * TN + i;
        if (n < NN) {
            __half2 h0 = __floats2half2_rn(acc[i][0], acc[i][1]);
            __half2 h1 = __floats2half2_rn(acc[i][2], acc[i][3]);
            __half2 h2 = __floats2half2_rn(acc[i][4], acc[i][5]);
            __half2 h3 = __floats2half2_rn(acc[i][6], acc[i][7]);
            uint4 u;
            u.x = *(unsigned*)&h0;
            u.y = *(unsigned*)&h1;
            u.z = *(unsigned*)&h2;
            u.w = *(unsigned*)&h3;
            *(uint4*)&g_hh[n * 128 + tc * TC] = u;
        }
    }
    // fused attention dots (fp32, from register accumulators): cols [tc*8, tc*8+8) lie in head tc>>2
    const int head = tc >> 2;
    const int col = tc * 8;
    float asv[8], adv[8];
#pragma unroll
    for (int j = 0; j < 8; j++) { asv[j] = att_src[col + j]; adv[j] = att_dst[col + j]; }
#pragma unroll
    for (int i = 0; i < TN; i++) {
        float s1 = 0.f, s2 = 0.f;
#pragma unroll
        for (int j = 0; j < 8; j++) {
            s1 = fmaf(acc[i][j], asv[j], s1);
            s2 = fmaf(acc[i][j], adv[j], s2);
        }
        s1 += __shfl_xor_sync(0xFFFFFFFF, s1, 1);
        s2 += __shfl_xor_sync(0xFFFFFFFF, s2, 1);
        s1 += __shfl_xor_sync(0xFFFFFFFF, s1, 2);
        s2 += __shfl_xor_sync(0xFFFFFFFF, s2, 2);
        int n = n0 + tn * TN + i;
        if ((tc & 3) == 0 && n < NN) {
            g_asrc[n * 4 + head] = s1;
            g_adst[n * 4 + head] = s2;
        }
    }
}

// ---------------- fused GAT: dual-edge softmax-free aggregate + dense1 + graph max pool ----------------
__global__ void __launch_bounds__(256) k_gat(const float* __restrict__ gat_bias,
                                             const float* __restrict__ d1w,
                                             const float* __restrict__ d1b,
                                             const int* __restrict__ batch) {
    __shared__ float ws[128 * 16];
    __shared__ float sb[16];
    __shared__ float sbias[128];
    __shared__ float stage[8][128];
    for (int i = threadIdx.x; i < 2048; i += 256) ws[i] = d1w[i];
    if (threadIdx.x < 16) sb[threadIdx.x] = d1b[threadIdx.x];
    if (threadIdx.x < 128) sbias[threadIdx.x] = gat_bias[threadIdx.x];
    __syncthreads();

    int w = threadIdx.x >> 5, lane = threadIdx.x & 31;
    int d = blockIdx.x * 8 + w;
    int base = g_off[d], deg = g_deg[d];
    int hd = lane >> 3;
    float adh = g_adst[d * 4 + hd];

    float psum = 0.f;
    float4 acc0 = make_float4(0.f, 0.f, 0.f, 0.f);
    float4 acc1 = make_float4(0.f, 0.f, 0.f, 0.f);
    for (int j0 = 0; j0 < deg; j0 += 32) {
        int pk = (j0 + lane < deg) ? g_csr[base + j0 + lane] : 0;
        int m = min(32, deg - j0);
        int jj = 0;
        for (; jj + 1 < m; jj += 2) {
            int pk0 = __shfl_sync(0xFFFFFFFF, pk, jj);
            int pk1 = __shfl_sync(0xFFFFFFFF, pk, jj + 1);
            int s0 = pk0 & 0xFFFFF, s1 = pk1 & 0xFFFFF;
            float a0 = g_asrc[s0 * 4 + hd];
            float a1 = g_asrc[s1 * 4 + hd];
            float p0 = __expf(lrelu(a0 + adh, 0.2f));
            float p1 = __expf(lrelu(a1 + adh, 0.2f));
            uint2 u0 = *(const uint2*)&g_hh[s0 * 128 + lane * 4];
            uint2 u1 = *(const uint2*)&g_hh[s1 * 128 + lane * 4];
            float2 h0a = __half22float2(*(__half2*)&u0.x);
            float2 h0b = __half22float2(*(__half2*)&u0.y);
            float2 h1a = __half22float2(*(__half2*)&u1.x);
            float2 h1b = __half22float2(*(__half2*)&u1.y);
            psum += p0 + p1;
            acc0.x = fmaf(h0a.x, p0, acc0.x); acc1.x = fmaf(h1a.x, p1, acc1.x);
            acc0.y = fmaf(h0a.y, p0, acc0.y); acc1.y = fmaf(h1a.y, p1, acc1.y);
            acc0.z = fmaf(h0b.x, p0, acc0.z); acc1.z = fmaf(h1b.x, p1, acc1.z);
            acc0.w = fmaf(h0b.y, p0, acc0.w); acc1.w = fmaf(h1b.y, p1, acc1.w);
        }
        if (jj < m) {
            int pk0 = __shfl_sync(0xFFFFFFFF, pk, jj);
            int s0 = pk0 & 0xFFFFF;
            float a0 = g_asrc[s0 * 4 + hd];
            float p0 = __expf(lrelu(a0 + adh, 0.2f));
            uint2 u0 = *(const uint2*)&g_hh[s0 * 128 + lane * 4];
            float2 h0a = __half22float2(*(__half2*)&u0.x);
            float2 h0b = __half22float2(*(__half2*)&u0.y);
            psum += p0;
            acc0.x = fmaf(h0a.x, p0, acc0.x);
            acc0.y = fmaf(h0a.y, p0, acc0.y);
            acc0.z = fmaf(h0b.x, p0, acc0.z);
            acc0.w = fmaf(h0b.y, p0, acc0.w);
        }
    }
    float4 acc = make_float4(acc0.x + acc1.x, acc0.y + acc1.y,
                             acc0.z + acc1.z, acc0.w + acc1.w);
    float rinv = (psum > 0.f) ? 1.f / psum : 0.f;
    stage[w][lane * 4 + 0] = lrelu(fmaf(acc.x, rinv, sbias[lane * 4 + 0]), 0.01f);
    stage[w][lane * 4 + 1] = lrelu(fmaf(acc.y, rinv, sbias[lane * 4 + 1]), 0.01f);
    stage[w][lane * 4 + 2] = lrelu(fmaf(acc.z, rinv, sbias[lane * 4 + 2]), 0.01f);
    stage[w][lane * 4 + 3] = lrelu(fmaf(acc.w, rinv, sbias[lane * 4 + 3]), 0.01f);
    __syncwarp();
    // dense1: j = lane&15, split-k over halves
    int j = lane & 15, half = lane >> 4;
    float o = (half == 0) ? sb[j] : 0.f;
    const float4* sr = (const float4*)&stage[w][half * 64];
#pragma unroll
    for (int k4 = 0; k4 < 16; k4++) {
        float4 av = sr[k4];
        int kb = half * 64 + k4 * 4;
        o = fmaf(av.x, ws[(kb + 0) * 16 + j], o);
        o = fmaf(av.y, ws[(kb + 1) * 16 + j], o);
        o = fmaf(av.z, ws[(kb + 2) * 16 + j], o);
        o = fmaf(av.w, ws[(kb + 3) * 16 + j], o);
    }
    o += __shfl_down_sync(0xFFFFFFFF, o, 16);
    if (lane < 16) {
        o = lrelu(o, 0.01f);
        atomicMaxF(&g_gmax[batch[d] * 16 + j], o);
    }
}

// ---------------- RGCN layer 1: quad-edge CSR aggregate + mean + root + relu -> z1 ----------------
__global__ void __launch_bounds__(256) k_rgcn1(const float* __restrict__ rb1, int dbase) {
    __shared__ float sinv[8][8];
    int w = threadIdx.x >> 5, lane = threadIdx.x & 31;
    int d = dbase + blockIdx.x * 8 + w;
    int base = g_off[d], deg = g_deg[d];
    int grp = lane >> 3, gl = lane & 7;

    int c0 = 0, c1 = 0, c2 = 0, c3 = 0, c4 = 0, c5 = 0, c6 = 0, c7 = 0;
    for (int i0 = 0; i0 < deg; i0 += 32) {
        int r = (i0 + lane < deg) ? ((g_csr[base + i0 + lane] >> 20) & 7) : 8;
        c0 += __popc(__ballot_sync(0xFFFFFFFF, r == 0));
        c1 += __popc(__ballot_sync(0xFFFFFFFF, r == 1));
        c2 += __popc(__ballot_sync(0xFFFFFFFF, r == 2));
        c3 += __popc(__ballot_sync(0xFFFFFFFF, r == 3));
        c4 += __popc(__ballot_sync(0xFFFFFFFF, r == 4));
        c5 += __popc(__ballot_sync(0xFFFFFFFF, r == 5));
        c6 += __popc(__ballot_sync(0xFFFFFFFF, r == 6));
        c7 += __popc(__ballot_sync(0xFFFFFFFF, r == 7));
    }
    if (lane < 8) {
        int cc = (lane == 0) ? c0 : (lane == 1) ? c1 : (lane == 2) ? c2 : (lane == 3) ? c3 :
                 (lane == 4) ? c4 : (lane == 5) ? c5 : (lane == 6) ? c6 : c7;
        sinv[w][lane] = cc ? 1.f / (float)cc : 0.f;
    }
    __syncwarp();

    float4 acc = make_float4(0.f, 0.f, 0.f, 0.f);
    for (int j0 = 0; j0 < deg; j0 += 32) {
        int pk = (j0 + lane < deg) ? g_csr[base + j0 + lane] : 0;
        int m = min(32, deg - j0);
        for (int jj = 0; jj < m; jj += 4) {
            int idx = jj + grp;
            bool ok = idx < m;
            int pkj = __shfl_sync(0xFFFFFFFF, pk, min(idx, 31));
            if (ok) {
                int s = pkj & 0xFFFFF, r = (pkj >> 20) & 7;
                float inv = sinv[w][r];
                uint2 u = *(const uint2*)&g_xw1[s * 288 + r * 32 + gl * 4];
                float2 va = __half22float2(*(__half2*)&u.x);
                float2 vb = __half22float2(*(__half2*)&u.y);
                acc.x = fmaf(va.x, inv, acc.x);
                acc.y = fmaf(va.y, inv, acc.y);
                acc.z = fmaf(vb.x, inv, acc.z);
                acc.w = fmaf(vb.y, inv, acc.w);
            }
        }
    }
    acc.x += __shfl_down_sync(0xFFFFFFFF, acc.x, 16);
    acc.y += __shfl_down_sync(0xFFFFFFFF, acc.y, 16);
    acc.z += __shfl_down_sync(0xFFFFFFFF, acc.z, 16);
    acc.w += __shfl_down_sync(0xFFFFFFFF, acc.w, 16);
    acc.x += __shfl_down_sync(0xFFFFFFFF, acc.x, 8);
    acc.y += __shfl_down_sync(0xFFFFFFFF, acc.y, 8);
    acc.z += __shfl_down_sync(0xFFFFFFFF, acc.z, 8);
    acc.w += __shfl_down_sync(0xFFFFFFFF, acc.w, 8);
    if (lane < 8) {
        uint2 u = *(const uint2*)&g_xw1[d * 288 + 256 + gl * 4];
        float2 ra = __half22float2(*(__half2*)&u.x);
        float2 rb = __half22float2(*(__half2*)&u.y);
        float4 b = *(const float4*)&rb1[gl * 4];
        float4 o;
        o.x = fmaxf(acc.x + ra.x + b.x, 0.f);
        o.y = fmaxf(acc.y + ra.y + b.y, 0.f);
        o.z = fmaxf(acc.z + rb.x + b.z, 0.f);
        o.w = fmaxf(acc.w + rb.y + b.w, 0.f);
        *(float4*)&g_z1[d * 32 + gl * 4] = o;
    }
}

// ---------------- RGCN layer 2: quad-edge CSR aggregate + mean + root + relu + graph sum pool ----------------
__global__ void __launch_bounds__(256) k_rgcn2(const float* __restrict__ rb2,
                                               const int* __restrict__ batch) {
    __shared__ float sinv[8][8];
    int w = threadIdx.x >> 5, lane = threadIdx.x & 31;
    int d = blockIdx.x * 8 + w;
    int base = g_off[d], deg = g_deg[d];
    int grp = lane >> 3, gl = lane & 7;

    int c0 = 0, c1 = 0, c2 = 0, c3 = 0, c4 = 0, c5 = 0, c6 = 0, c7 = 0;
    for (int i0 = 0; i0 < deg; i0 += 32) {
        int r = (i0 + lane < deg) ? ((g_csr[base + i0 + lane] >> 20) & 7) : 8;
        c0 += __popc(__ballot_sync(0xFFFFFFFF, r == 0));
        c1 += __popc(__ballot_sync(0xFFFFFFFF, r == 1));
        c2 += __popc(__ballot_sync(0xFFFFFFFF, r == 2));
        c3 += __popc(__ballot_sync(0xFFFFFFFF, r == 3));
        c4 += __popc(__ballot_sync(0xFFFFFFFF, r == 4));
        c5 += __popc(__ballot_sync(0xFFFFFFFF, r == 5));
        c6 += __popc(__ballot_sync(0xFFFFFFFF, r == 6));
        c7 += __popc(__ballot_sync(0xFFFFFFFF, r == 7));
    }
    if (lane < 8) {
        int cc = (lane == 0) ? c0 : (lane == 1) ? c1 : (lane == 2) ? c2 : (lane == 3) ? c3 :
                 (lane == 4) ? c4 : (lane == 5) ? c5 : (lane == 6) ? c6 : c7;
        sinv[w][lane] = cc ? 1.f / (float)cc : 0.f;
    }
    __syncwarp();

    float2 acc = make_float2(0.f, 0.f);
    for (int j0 = 0; j0 < deg; j0 += 32) {
        int pk = (j0 + lane < deg) ? g_csr[base + j0 + lane] : 0;
        int m = min(32, deg - j0);
        for (int jj = 0; jj < m; jj += 4) {
            int idx = jj + grp;
            bool ok = idx < m;
            int pkj = __shfl_sync(0xFFFFFFFF, pk, min(idx, 31));
            if (ok) {
                int s = pkj & 0xFFFFF, r = (pkj >> 20) & 7;
                float inv = sinv[w][r];
                unsigned u = *(const unsigned*)&g_xw2[s * 144 + r * 16 + gl * 2];
                float2 v = __half22float2(*(__half2*)&u);
                acc.x = fmaf(v.x, inv, acc.x);
                acc.y = fmaf(v.y, inv, acc.y);
            }
        }
    }
    acc.x += __shfl_down_sync(0xFFFFFFFF, acc.x, 16);
    acc.y += __shfl_down_sync(0xFFFFFFFF, acc.y, 16);
    acc.x += __shfl_down_sync(0xFFFFFFFF, acc.x, 8);
    acc.y += __shfl_down_sync(0xFFFFFFFF, acc.y, 8);
    if (lane < 8) {
        unsigned u = *(const unsigned*)&g_xw2[d * 144 + 128 + gl * 2];
        float2 root = __half22float2(*(__half2*)&u);
        float2 b = *(const float2*)&rb2[gl * 2];
        float zx = fmaxf(acc.x + root.x + b.x, 0.f);
        float zy = fmaxf(acc.y + root.y + b.y, 0.f);
        int g = batch[d];
        atomicAdd(&g_gsum[g * 16 + gl * 2 + 0], zx);
        atomicAdd(&g_gsum[g * 16 + gl * 2 + 1], zy);
        if (lane == 0) atomicAdd(&g_npg[g], 1.f);
    }
}

// ---------------- final readout ----------------
__global__ void k_final(const float* __restrict__ dw, const float* __restrict__ db,
                        float* __restrict__ out) {
    int g = threadIdx.x;
    float inv = 1.f / g_npg[g];
    float acc = db[0];
#pragma unroll
    for (int c = 0; c < 16; c++) {
        acc = fmaf(g_gmax[g * 16 + c], dw[c], acc);
        acc = fmaf(g_gsum[g * 16 + c] * inv, dw[16 + c], acc);
    }
    out[g] = acc;
}

// ---------------- launch ----------------
extern "C" void kernel_launch(void* const* d_in, const int* in_sizes, int n_in,
                              void* d_out, int out_size) {
    const float* x        = (const float*)d_in[0];
    const int*   ei       = (const int*)d_in[1];
    const int*   et       = (const int*)d_in[2];
    const int*   batch    = (const int*)d_in[3];
    const float* gat_w    = (const float*)d_in[4];
    const float* att_src  = (const float*)d_in[5];
    const float* att_dst  = (const float*)d_in[6];
    const float* gat_bias = (const float*)d_in[7];
    const float* d1w      = (const float*)d_in[8];
    const float* d1b      = (const float*)d_in[9];
    const float* rw1      = (const float*)d_in[10];
    const float* root1    = (const float*)d_in[11];
    const float* rb1      = (const float*)d_in[12];
    const float* rw2      = (const float*)d_in[13];
    const float* root2    = (const float*)d_in[14];
    const float* rb2      = (const float*)d_in[15];
    const float* dw       = (const float*)d_in[16];
    const float* db       = (const float*)d_in[17];
    float* out = (float*)d_out;

    const int* src = ei;
    const int* dst = ei + EE;

    void *p_w1, *p_xw1, *p_w2, *p_xw2, *p_z1;
    cudaGetSymbolAddress(&p_w1, g_w1);
    cudaGetSymbolAddress(&p_xw1, g_xw1);
    cudaGetSymbolAddress(&p_w2, g_w2);
    cudaGetSymbolAddress(&p_xw2, g_xw2);
    cudaGetSymbolAddress(&p_z1, g_z1);

    cudaStream_t s2 = g_fork.s2;
    cudaStream_t s3 = g_fork.s3;

    cudaEventRecord(g_fork.evStart, 0);
    cudaStreamWaitEvent(s2, g_fork.evStart, 0);
    cudaStreamWaitEvent(s3, g_fork.evStart, 0);

    // s2: init + CSR build (off the critical path)
    k_init<<<(NN + 255) / 256, 256, 0, s2>>>();
    k_count<<<EE / 256, 256, 0, s2>>>(dst);
    k_scan1<<<NBLK, 1024, 0, s2>>>();
    k_scan2<<<1, 128, 0, s2>>>();
    k_scan3<<<NBLK, 1024, 0, s2>>>();
    k_scatter<<<EE / 256, 256, 0, s2>>>(src, dst, et);
    cudaEventRecord(g_fork.evCSR, s2);

    // s3: GAT transform (+att dots), then fused GAT after CSR ready
    k_gemm_h<<<(NN + 47) / 48, 96, 0, s3>>>(x, gat_w, att_src, att_dst);
    cudaStreamWaitEvent(s3, g_fork.evCSR, 0);
    k_gat<<<NN / 8, 256, 0, s3>>>(gat_bias, d1w, d1b, batch);
    cudaEventRecord(g_fork.evGat, s3);

    // main: pack + xw1 GEMM immediately (overlaps CSR + gemm_h)
    k_pack<<<(64 * 288 + 32 * 144 + 255) / 256, 256>>>(rw1, root1, rw2, root2);
    k_gemm<64, 288, 96, 64, 8, 8><<<dim3((NN + 63) / 64, 3), 96>>>(x, (const float*)p_w1, (__half*)p_xw1, 0);
    cudaStreamWaitEvent(0, g_fork.evCSR, 0);

    // pipelined rgcn1 / xw2 halves: [0, SPLIT) then [SPLIT, NN)
    k_rgcn1<<<SPLIT / 8, 256>>>(rb1, 0);
    cudaEventRecord(g_fork.evR1, 0);
    k_rgcn1<<<(NN - SPLIT) / 8, 256>>>(rb1, SPLIT);

    // s2: xw2 for the first half while main does rgcn1_hi
    cudaStreamWaitEvent(s2, g_fork.evR1, 0);
    k_gemm<32, 144, 144, 64, 8, 8><<<dim3(SPLIT / 64, 1), 144, 0, s2>>>(
        (const float*)p_z1, (const float*)p_w2, (__half*)p_xw2, 0);
    cudaEventRecord(g_fork.evX2lo, s2);

    // main: xw2 for the second half, then join and rgcn2
    k_gemm<32, 144, 144, 64, 8, 8><<<dim3((NN - SPLIT + 63) / 64, 1), 144>>>(
        (const float*)p_z1, (const float*)p_w2, (__half*)p_xw2, SPLIT);
    cudaStreamWaitEvent(0, g_fork.evX2lo, 0);
    k_rgcn2<<<NN / 8, 256>>>(rb2, batch);

    // join GAT branch
    cudaStreamWaitEvent(0, g_fork.evGat, 0);
    k_final<<<1, 256>>>(dw, db, out);
}

// round 17
// speedup vs baseline: 1.4387x; 1.4387x over previous
#include <cuda_runtime.h>
#include <cuda_fp16.h>

#define NN 100000
#define EE 1600000
#define GG 256
#define NBLK 98   // ceil(NN/1024) for scan
#define SPLIT 50048  // node split for rgcn1/xw2 pipeline (multiple of 64 and 8)

// ---------------- scratch (__device__ globals, allocation-free) ----------------
__device__ __half g_hh[NN * 128];     // GAT transformed features (fp16)
__device__ float g_asrc[NN * 4];
__device__ float g_adst[NN * 4];
__device__ float g_w1[64 * 288];      // packed [k][r*32+c | root 256..287]
__device__ float g_w2[32 * 144];      // packed [k][r*16+c | root 128..143]
__device__ __half g_xw1[NN * 288];    // fp16
__device__ float g_z1[NN * 32];
__device__ __half g_xw2[NN * 144];    // fp16
__device__ float g_gmax[GG * 16];
__device__ float g_gsum[GG * 16];
__device__ float g_npg[GG];
// CSR
__device__ int g_deg[NN];
__device__ int g_off[NN];
__device__ int g_cur[NN];
__device__ int g_scan[NBLK * 1024];
__device__ int g_bsum[NBLK];
__device__ int g_bpre[NBLK];
__device__ int g_csr[EE];             // src | (rel<<20)

// ---------------- persistent streams/events (host-side objects only) ----------------
struct ForkCtx {
    cudaStream_t s2, s3;
    cudaEvent_t evStart, evCSR, evR1, evX2lo, evGat;
    ForkCtx() {
        cudaStreamCreateWithFlags(&s2, cudaStreamNonBlocking);
        cudaStreamCreateWithFlags(&s3, cudaStreamNonBlocking);
        cudaEventCreateWithFlags(&evStart, cudaEventDisableTiming);
        cudaEventCreateWithFlags(&evCSR, cudaEventDisableTiming);
        cudaEventCreateWithFlags(&evR1, cudaEventDisableTiming);
        cudaEventCreateWithFlags(&evX2lo, cudaEventDisableTiming);
        cudaEventCreateWithFlags(&evGat, cudaEventDisableTiming);
    }
};
static ForkCtx g_fork;

// ---------------- helpers ----------------
__device__ __forceinline__ float lrelu(float x, float s) {
    return x > 0.f ? x : x * s;
}

__device__ __forceinline__ void atomicMaxF(float* addr, float v) {
    if (v >= 0.f) atomicMax((int*)addr, __float_as_int(v));
    else          atomicMin((unsigned int*)addr, __float_as_uint(v));
}

// ---------------- init ----------------
__global__ void k_init() {
    int i = blockIdx.x * 256 + threadIdx.x;
    const float NEG_INF = __int_as_float(0xff800000);
    if (i < NN) g_deg[i] = 0;
    if (i < GG * 16) { g_gsum[i] = 0.f; g_gmax[i] = NEG_INF; }
    if (i < GG) g_npg[i] = 0.f;
}

// ---------------- pack relation weights ----------------
__global__ void k_pack(const float* __restrict__ rw1, const float* __restrict__ root1,
                       const float* __restrict__ rw2, const float* __restrict__ root2) {
    int i = blockIdx.x * 256 + threadIdx.x;
    if (i < 64 * 288) {
        int k = i / 288, j = i % 288;
        g_w1[i] = (j < 256) ? rw1[((j >> 5) * 64 + k) * 32 + (j & 31)]
                            : root1[k * 32 + (j - 256)];
    } else if (i < 64 * 288 + 32 * 144) {
        int t = i - 64 * 288;
        int k = t / 144, j = t % 144;
        g_w2[t] = (j < 128) ? rw2[((j >> 4) * 32 + k) * 16 + (j & 15)]
                            : root2[k * 16 + (j - 128)];
    }
}

// ---------------- CSR build ----------------
__global__ void k_count(const int* __restrict__ dst) {
    int e = blockIdx.x * 256 + threadIdx.x;
    atomicAdd(&g_deg[dst[e]], 1);
}

__global__ void k_scan1() {
    __shared__ int s[1024];
    int t = threadIdx.x;
    int i = blockIdx.x * 1024 + t;
    int v = (i < NN) ? g_deg[i] : 0;
    s[t] = v;
    __syncthreads();
    for (int ofs = 1; ofs < 1024; ofs <<= 1) {
        int add = (t >= ofs) ? s[t - ofs] : 0;
        __syncthreads();
        s[t] += add;
        __syncthreads();
    }
    g_scan[i] = s[t];
    if (t == 1023) g_bsum[blockIdx.x] = s[1023];
}

__global__ void k_scan2() {
    __shared__ int s[128];
    int t = threadIdx.x;
    int v = (t < NBLK) ? g_bsum[t] : 0;
    s[t] = v;
    __syncthreads();
    for (int ofs = 1; ofs < 128; ofs <<= 1) {
        int add = (t >= ofs) ? s[t - ofs] : 0;
        __syncthreads();
        s[t] += add;
        __syncthreads();
    }
    if (t < NBLK) g_bpre[t] = s[t] - v;  // exclusive
}

__global__ void k_scan3() {
    int i = blockIdx.x * 1024 + threadIdx.x;
    if (i < NN) {
        int excl = g_scan[i] - g_deg[i] + g_bpre[blockIdx.x];
        g_off[i] = excl;
        g_cur[i] = excl;
    }
}

__global__ void k_scatter(const int* __restrict__ src, const int* __restrict__ dst,
                          const int* __restrict__ et) {
    int e = blockIdx.x * 256 + threadIdx.x;
    int d = dst[e];
    int p = atomicAdd(&g_cur[d], 1);
    g_csr[p] = src[e] | (et[e] << 20);
}

// ---------------- SIMT smem GEMM: C[N, OC_TOTAL] = A[N, IC] @ W[IC, OC_TOTAL], fp16 out ----------------
template<int IC, int OC_TOTAL, int OC_CHUNK, int NPB, int TN, int TC>
__global__ void __launch_bounds__((NPB / TN) * (OC_CHUNK / TC))
k_gemm(const float* __restrict__ A, const float* __restrict__ W, __half* __restrict__ C,
       int nbase) {
    constexpr int THREADS = (NPB / TN) * (OC_CHUNK / TC);
    __shared__ float ws[IC * OC_CHUNK];
    __shared__ float xs[NPB * IC];
    const int col0 = blockIdx.y * OC_CHUNK;

    for (int i = threadIdx.x; i < IC * OC_CHUNK / 4; i += THREADS) {
        int k = (i * 4) / OC_CHUNK, j = (i * 4) % OC_CHUNK;
        *(float4*)&ws[i * 4] = *(const float4*)&W[k * OC_TOTAL + col0 + j];
    }
    const int n0 = nbase + blockIdx.x * NPB;
    for (int i = threadIdx.x; i < NPB * IC / 4; i += THREADS) {
        int r = (i * 4) / IC, k = (i * 4) % IC;
        int n = n0 + r;
        float4 v = make_float4(0.f, 0.f, 0.f, 0.f);
        if (n < NN) v = *(const float4*)&A[n * IC + k];
        *(float4*)&xs[i * 4] = v;
    }
    __syncthreads();

    const int tc = threadIdx.x % (OC_CHUNK / TC);
    const int tn = threadIdx.x / (OC_CHUNK / TC);
    float acc[TN][TC];
#pragma unroll
    for (int i = 0; i < TN; i++)
#pragma unroll
        for (int j = 0; j < TC; j++) acc[i][j] = 0.f;

    const float* xb = &xs[tn * TN * IC];
    const float* wb = &ws[tc * TC];
    for (int k4 = 0; k4 < IC / 4; k4++) {
        float4 xv[TN];
#pragma unroll
        for (int i = 0; i < TN; i++) xv[i] = *(const float4*)&xb[i * IC + k4 * 4];
#pragma unroll
        for (int kk = 0; kk < 4; kk++) {
            float wr[TC];
#pragma unroll
            for (int j4 = 0; j4 < TC / 4; j4++)
                *(float4*)&wr[j4 * 4] = *(const float4*)&wb[(k4 * 4 + kk) * OC_CHUNK + j4 * 4];
#pragma unroll
            for (int i = 0; i < TN; i++) {
                float xvk = (kk == 0) ? xv[i].x : (kk == 1) ? xv[i].y : (kk == 2) ? xv[i].z : xv[i].w;
#pragma unroll
                for (int j = 0; j < TC; j++) acc[i][j] = fmaf(xvk, wr[j], acc[i][j]);
            }
        }
    }
#pragma unroll
    for (int i = 0; i < TN; i++) {
        int n = n0 + tn * TN + i;
        if (n < NN) {
#pragma unroll
            for (int j4 = 0; j4 < TC / 4; j4++) {
                __half2 h0 = __floats2half2_rn(acc[i][j4 * 4 + 0], acc[i][j4 * 4 + 1]);
                __half2 h1 = __floats2half2_rn(acc[i][j4 * 4 + 2], acc[i][j4 * 4 + 3]);
                uint2 u;
                u.x = *(unsigned*)&h0;
                u.y = *(unsigned*)&h1;
                *(uint2*)&C[n * OC_TOTAL + col0 + tc * TC + j4 * 4] = u;
            }
        }
    }
}

// ---------------- GAT transform GEMM with fused attention-dot epilogue (fp16 h out) ----------------
__global__ void __launch_bounds__(96)
k_gemm_h(const float* __restrict__ A, const float* __restrict__ W,
         const float* __restrict__ att_src, const float* __restrict__ att_dst) {
    constexpr int IC = 64, OC = 128, NPB = 48, TN = 8, TC = 8, THREADS = 96;
    __shared__ float ws[IC * OC];
    __shared__ float xs[NPB * IC];

    for (int i = threadIdx.x; i < IC * OC / 4; i += THREADS)
        *(float4*)&ws[i * 4] = *(const float4*)&W[i * 4];
    const int n0 = blockIdx.x * NPB;
    for (int i = threadIdx.x; i < NPB * IC / 4; i += THREADS) {
        int r = (i * 4) / IC, k = (i * 4) % IC;
        int n = n0 + r;
        float4 v = make_float4(0.f, 0.f, 0.f, 0.f);
        if (n < NN) v = *(const float4*)&A[n * IC + k];
        *(float4*)&xs[i * 4] = v;
    }
    __syncthreads();

    const int tc = threadIdx.x % 16;
    const int tn = threadIdx.x / 16;
    float acc[TN][TC];
#pragma unroll
    for (int i = 0; i < TN; i++)
#pragma unroll
        for (int j = 0; j < TC; j++) acc[i][j] = 0.f;

    const float* xb = &xs[tn * TN * IC];
    const float* wb = &ws[tc * TC];
    for (int k4 = 0; k4 < IC / 4; k4++) {
        float4 xv[TN];
#pragma unroll
        for (int i = 0; i < TN; i++) xv[i] = *(const float4*)&xb[i * IC + k4 * 4];
#pragma unroll
        for (int kk = 0; kk < 4; kk++) {
            float wr[TC];
#pragma unroll
            for (int j4 = 0; j4 < TC / 4; j4++)
                *(float4*)&wr[j4 * 4] = *(const float4*)&wb[(k4 * 4 + kk) * OC + j4 * 4];
#pragma unroll
            for (int i = 0; i < TN; i++) {
                float xvk = (kk == 0) ? xv[i].x : (kk == 1) ? xv[i].y : (kk == 2) ? xv[i].z : xv[i].w;
#pragma unroll
                for (int j = 0; j < TC; j++) acc[i][j] = fmaf(xvk, wr[j], acc[i][j]);
            }
        }
    }
    // store h as fp16 (8 cols = 4 half2 = one uint4)
#pragma unroll
    for (int i = 0; i < TN; i++) {
        int n = n0 + tn * TN + i;
        if (n < NN) {
            __half2 h0 = __floats2half2_rn(acc[i][0], acc[i][1]);
            __half2 h1 = __floats2half2_rn(acc[i][2], acc[i][3]);
            __half2 h2 = __floats2half2_rn(acc[i][4], acc[i][5]);
            __half2 h3 = __floats2half2_rn(acc[i][6], acc[i][7]);
            uint4 u;
            u.x = *(unsigned*)&h0;
            u.y = *(unsigned*)&h1;
            u.z = *(unsigned*)&h2;
            u.w = *(unsigned*)&h3;
            *(uint4*)&g_hh[n * 128 + tc * TC] = u;
        }
    }
    // fused attention dots (fp32, from register accumulators): cols [tc*8, tc*8+8) lie in head tc>>2
    const int head = tc >> 2;
    const int col = tc * 8;
    float asv[8], adv[8];
#pragma unroll
    for (int j = 0; j < 8; j++) { asv[j] = att_src[col + j]; adv[j] = att_dst[col + j]; }
#pragma unroll
    for (int i = 0; i < TN; i++) {
        float s1 = 0.f, s2 = 0.f;
#pragma unroll
        for (int j = 0; j < 8; j++) {
            s1 = fmaf(acc[i][j], asv[j], s1);
            s2 = fmaf(acc[i][j], adv[j], s2);
        }
        s1 += __shfl_xor_sync(0xFFFFFFFF, s1, 1);
        s2 += __shfl_xor_sync(0xFFFFFFFF, s2, 1);
        s1 += __shfl_xor_sync(0xFFFFFFFF, s1, 2);
        s2 += __shfl_xor_sync(0xFFFFFFFF, s2, 2);
        int n = n0 + tn * TN + i;
        if ((tc & 3) == 0 && n < NN) {
            g_asrc[n * 4 + head] = s1;
            g_adst[n * 4 + head] = s2;
        }
    }
}

// ---------------- fused GAT: dual-edge softmax-free aggregate + dense1 + graph max pool ----------------
__global__ void __launch_bounds__(256) k_gat(const float* __restrict__ gat_bias,
                                             const float* __restrict__ d1w,
                                             const float* __restrict__ d1b,
                                             const int* __restrict__ batch) {
    __shared__ float ws[128 * 16];
    __shared__ float sb[16];
    __shared__ float sbias[128];
    __shared__ float stage[8][128];
    for (int i = threadIdx.x; i < 2048; i += 256) ws[i] = d1w[i];
    if (threadIdx.x < 16) sb[threadIdx.x] = d1b[threadIdx.x];
    if (threadIdx.x < 128) sbias[threadIdx.x] = gat_bias[threadIdx.x];
    __syncthreads();

    int w = threadIdx.x >> 5, lane = threadIdx.x & 31;
    int d = blockIdx.x * 8 + w;
    int base = g_off[d], deg = g_deg[d];
    int hd = lane >> 3;
    float adh = g_adst[d * 4 + hd];

    float psum = 0.f;
    float4 acc0 = make_float4(0.f, 0.f, 0.f, 0.f);
    float4 acc1 = make_float4(0.f, 0.f, 0.f, 0.f);
    for (int j0 = 0; j0 < deg; j0 += 32) {
        int pk = (j0 + lane < deg) ? g_csr[base + j0 + lane] : 0;
        int m = min(32, deg - j0);
        int jj = 0;
        for (; jj + 1 < m; jj += 2) {
            int pk0 = __shfl_sync(0xFFFFFFFF, pk, jj);
            int pk1 = __shfl_sync(0xFFFFFFFF, pk, jj + 1);
            int s0 = pk0 & 0xFFFFF, s1 = pk1 & 0xFFFFF;
            float a0 = g_asrc[s0 * 4 + hd];
            float a1 = g_asrc[s1 * 4 + hd];
            float p0 = __expf(lrelu(a0 + adh, 0.2f));
            float p1 = __expf(lrelu(a1 + adh, 0.2f));
            uint2 u0 = *(const uint2*)&g_hh[s0 * 128 + lane * 4];
            uint2 u1 = *(const uint2*)&g_hh[s1 * 128 + lane * 4];
            float2 h0a = __half22float2(*(__half2*)&u0.x);
            float2 h0b = __half22float2(*(__half2*)&u0.y);
            float2 h1a = __half22float2(*(__half2*)&u1.x);
            float2 h1b = __half22float2(*(__half2*)&u1.y);
            psum += p0 + p1;
            acc0.x = fmaf(h0a.x, p0, acc0.x); acc1.x = fmaf(h1a.x, p1, acc1.x);
            acc0.y = fmaf(h0a.y, p0, acc0.y); acc1.y = fmaf(h1a.y, p1, acc1.y);
            acc0.z = fmaf(h0b.x, p0, acc0.z); acc1.z = fmaf(h1b.x, p1, acc1.z);
            acc0.w = fmaf(h0b.y, p0, acc0.w); acc1.w = fmaf(h1b.y, p1, acc1.w);
        }
        if (jj < m) {
            int pk0 = __shfl_sync(0xFFFFFFFF, pk, jj);
            int s0 = pk0 & 0xFFFFF;
            float a0 = g_asrc[s0 * 4 + hd];
            float p0 = __expf(lrelu(a0 + adh, 0.2f));
            uint2 u0 = *(const uint2*)&g_hh[s0 * 128 + lane * 4];
            float2 h0a = __half22float2(*(__half2*)&u0.x);
            float2 h0b = __half22float2(*(__half2*)&u0.y);
            psum += p0;
            acc0.x = fmaf(h0a.x, p0, acc0.x);
            acc0.y = fmaf(h0a.y, p0, acc0.y);
            acc0.z = fmaf(h0b.x, p0, acc0.z);
            acc0.w = fmaf(h0b.y, p0, acc0.w);
        }
    }
    float4 acc = make_float4(acc0.x + acc1.x, acc0.y + acc1.y,
                             acc0.z + acc1.z, acc0.w + acc1.w);
    float rinv = (psum > 0.f) ? 1.f / psum : 0.f;
    stage[w][lane * 4 + 0] = lrelu(fmaf(acc.x, rinv, sbias[lane * 4 + 0]), 0.01f);
    stage[w][lane * 4 + 1] = lrelu(fmaf(acc.y, rinv, sbias[lane * 4 + 1]), 0.01f);
    stage[w][lane * 4 + 2] = lrelu(fmaf(acc.z, rinv, sbias[lane * 4 + 2]), 0.01f);
    stage[w][lane * 4 + 3] = lrelu(fmaf(acc.w, rinv, sbias[lane * 4 + 3]), 0.01f);
    __syncwarp();
    // dense1: j = lane&15, split-k over halves
    int j = lane & 15, half = lane >> 4;
    float o = (half == 0) ? sb[j] : 0.f;
    const float4* sr = (const float4*)&stage[w][half * 64];
#pragma unroll
    for (int k4 = 0; k4 < 16; k4++) {
        float4 av = sr[k4];
        int kb = half * 64 + k4 * 4;
        o = fmaf(av.x, ws[(kb + 0) * 16 + j], o);
        o = fmaf(av.y, ws[(kb + 1) * 16 + j], o);
        o = fmaf(av.z, ws[(kb + 2) * 16 + j], o);
        o = fmaf(av.w, ws[(kb + 3) * 16 + j], o);
    }
    o += __shfl_down_sync(0xFFFFFFFF, o, 16);
    if (lane < 16) {
        o = lrelu(o, 0.01f);
        atomicMaxF(&g_gmax[batch[d] * 16 + j], o);
    }
}

// ---------------- RGCN layer 1: quad-edge CSR aggregate + mean + root + relu -> z1 ----------------
__global__ void __launch_bounds__(256) k_rgcn1(const float* __restrict__ rb1, int dbase) {
    __shared__ float sinv[8][8];
    int w = threadIdx.x >> 5, lane = threadIdx.x & 31;
    int d = dbase + blockIdx.x * 8 + w;
    int base = g_off[d], deg = g_deg[d];
    int grp = lane >> 3, gl = lane & 7;

    int c0 = 0, c1 = 0, c2 = 0, c3 = 0, c4 = 0, c5 = 0, c6 = 0, c7 = 0;
    for (int i0 = 0; i0 < deg; i0 += 32) {
        int r = (i0 + lane < deg) ? ((g_csr[base + i0 + lane] >> 20) & 7) : 8;
        c0 += __popc(__ballot_sync(0xFFFFFFFF, r == 0));
        c1 += __popc(__ballot_sync(0xFFFFFFFF, r == 1));
        c2 += __popc(__ballot_sync(0xFFFFFFFF, r == 2));
        c3 += __popc(__ballot_sync(0xFFFFFFFF, r == 3));
        c4 += __popc(__ballot_sync(0xFFFFFFFF, r == 4));
        c5 += __popc(__ballot_sync(0xFFFFFFFF, r == 5));
        c6 += __popc(__ballot_sync(0xFFFFFFFF, r == 6));
        c7 += __popc(__ballot_sync(0xFFFFFFFF, r == 7));
    }
    if (lane < 8) {
        int cc = (lane == 0) ? c0 : (lane == 1) ? c1 : (lane == 2) ? c2 : (lane == 3) ? c3 :
                 (lane == 4) ? c4 : (lane == 5) ? c5 : (lane == 6) ? c6 : c7;
        sinv[w][lane] = cc ? 1.f / (float)cc : 0.f;
    }
    __syncwarp();

    float4 acc = make_float4(0.f, 0.f, 0.f, 0.f);
    for (int j0 = 0; j0 < deg; j0 += 32) {
        int pk = (j0 + lane < deg) ? g_csr[base + j0 + lane] : 0;
        int m = min(32, deg - j0);
        for (int jj = 0; jj < m; jj += 4) {
            int idx = jj + grp;
            bool ok = idx < m;
            int pkj = __shfl_sync(0xFFFFFFFF, pk, min(idx, 31));
            if (ok) {
                int s = pkj & 0xFFFFF, r = (pkj >> 20) & 7;
                float inv = sinv[w][r];
                uint2 u = *(const uint2*)&g_xw1[s * 288 + r * 32 + gl * 4];
                float2 va = __half22float2(*(__half2*)&u.x);
                float2 vb = __half22float2(*(__half2*)&u.y);
                acc.x = fmaf(va.x, inv, acc.x);
                acc.y = fmaf(va.y, inv, acc.y);
                acc.z = fmaf(vb.x, inv, acc.z);
                acc.w = fmaf(vb.y, inv, acc.w);
            }
        }
    }
    acc.x += __shfl_down_sync(0xFFFFFFFF, acc.x, 16);
    acc.y += __shfl_down_sync(0xFFFFFFFF, acc.y, 16);
    acc.z += __shfl_down_sync(0xFFFFFFFF, acc.z, 16);
    acc.w += __shfl_down_sync(0xFFFFFFFF, acc.w, 16);
    acc.x += __shfl_down_sync(0xFFFFFFFF, acc.x, 8);
    acc.y += __shfl_down_sync(0xFFFFFFFF, acc.y, 8);
    acc.z += __shfl_down_sync(0xFFFFFFFF, acc.z, 8);
    acc.w += __shfl_down_sync(0xFFFFFFFF, acc.w, 8);
    if (lane < 8) {
        uint2 u = *(const uint2*)&g_xw1[d * 288 + 256 + gl * 4];
        float2 ra = __half22float2(*(__half2*)&u.x);
        float2 rb = __half22float2(*(__half2*)&u.y);
        float4 b = *(const float4*)&rb1[gl * 4];
        float4 o;
        o.x = fmaxf(acc.x + ra.x + b.x, 0.f);
        o.y = fmaxf(acc.y + ra.y + b.y, 0.f);
        o.z = fmaxf(acc.z + rb.x + b.z, 0.f);
        o.w = fmaxf(acc.w + rb.y + b.w, 0.f);
        *(float4*)&g_z1[d * 32 + gl * 4] = o;
    }
}

// ---------------- RGCN layer 2: quad-edge CSR aggregate + mean + root + relu + graph sum pool ----------------
__global__ void __launch_bounds__(256) k_rgcn2(const float* __restrict__ rb2,
                                               const int* __restrict__ batch) {
    __shared__ float sinv[8][8];
    int w = threadIdx.x >> 5, lane = threadIdx.x & 31;
    int d = blockIdx.x * 8 + w;
    int base = g_off[d], deg = g_deg[d];
    int grp = lane >> 3, gl = lane & 7;

    int c0 = 0, c1 = 0, c2 = 0, c3 = 0, c4 = 0, c5 = 0, c6 = 0, c7 = 0;
    for (int i0 = 0; i0 < deg; i0 += 32) {
        int r = (i0 + lane < deg) ? ((g_csr[base + i0 + lane] >> 20) & 7) : 8;
        c0 += __popc(__ballot_sync(0xFFFFFFFF, r == 0));
        c1 += __popc(__ballot_sync(0xFFFFFFFF, r == 1));
        c2 += __popc(__ballot_sync(0xFFFFFFFF, r == 2));
        c3 += __popc(__ballot_sync(0xFFFFFFFF, r == 3));
        c4 += __popc(__ballot_sync(0xFFFFFFFF, r == 4));
        c5 += __popc(__ballot_sync(0xFFFFFFFF, r == 5));
        c6 += __popc(__ballot_sync(0xFFFFFFFF, r == 6));
        c7 += __popc(__ballot_sync(0xFFFFFFFF, r == 7));
    }
    if (lane < 8) {
        int cc = (lane == 0) ? c0 : (lane == 1) ? c1 : (lane == 2) ? c2 : (lane == 3) ? c3 :
                 (lane == 4) ? c4 : (lane == 5) ? c5 : (lane == 6) ? c6 : c7;
        sinv[w][lane] = cc ? 1.f / (float)cc : 0.f;
    }
    __syncwarp();

    float2 acc = make_float2(0.f, 0.f);
    for (int j0 = 0; j0 < deg; j0 += 32) {
        int pk = (j0 + lane < deg) ? g_csr[base + j0 + lane] : 0;
        int m = min(32, deg - j0);
        for (int jj = 0; jj < m; jj += 4) {
            int idx = jj + grp;
            bool ok = idx < m;
            int pkj = __shfl_sync(0xFFFFFFFF, pk, min(idx, 31));
            if (ok) {
                int s = pkj & 0xFFFFF, r = (pkj >> 20) & 7;
                float inv = sinv[w][r];
                unsigned u = *(const unsigned*)&g_xw2[s * 144 + r * 16 + gl * 2];
                float2 v = __half22float2(*(__half2*)&u);
                acc.x = fmaf(v.x, inv, acc.x);
                acc.y = fmaf(v.y, inv, acc.y);
            }
        }
    }
    acc.x += __shfl_down_sync(0xFFFFFFFF, acc.x, 16);
    acc.y += __shfl_down_sync(0xFFFFFFFF, acc.y, 16);
    acc.x += __shfl_down_sync(0xFFFFFFFF, acc.x, 8);
    acc.y += __shfl_down_sync(0xFFFFFFFF, acc.y, 8);
    if (lane < 8) {
        unsigned u = *(const unsigned*)&g_xw2[d * 144 + 128 + gl * 2];
        float2 root = __half22float2(*(__half2*)&u);
        float2 b = *(const float2*)&rb2[gl * 2];
        float zx = fmaxf(acc.x + root.x + b.x, 0.f);
        float zy = fmaxf(acc.y + root.y + b.y, 0.f);
        int g = batch[d];
        atomicAdd(&g_gsum[g * 16 + gl * 2 + 0], zx);
        atomicAdd(&g_gsum[g * 16 + gl * 2 + 1], zy);
        if (lane == 0) atomicAdd(&g_npg[g], 1.f);
    }
}

// ---------------- final readout ----------------
__global__ void k_final(const float* __restrict__ dw, const float* __restrict__ db,
                        float* __restrict__ out) {
    int g = threadIdx.x;
    float inv = 1.f / g_npg[g];
    float acc = db[0];
#pragma unroll
    for (int c = 0; c < 16; c++) {
        acc = fmaf(g_gmax[g * 16 + c], dw[c], acc);
        acc = fmaf(g_gsum[g * 16 + c] * inv, dw[16 + c], acc);
    }
    out[g] = acc;
}

// ---------------- launch ----------------
extern "C" void kernel_launch(void* const* d_in, const int* in_sizes, int n_in,
                              void* d_out, int out_size) {
    const float* x        = (const float*)d_in[0];
    const int*   ei       = (const int*)d_in[1];
    const int*   et       = (const int*)d_in[2];
    const int*   batch    = (const int*)d_in[3];
    const float* gat_w    = (const float*)d_in[4];
    const float* att_src  = (const float*)d_in[5];
    const float* att_dst  = (const float*)d_in[6];
    const float* gat_bias = (const float*)d_in[7];
    const float* d1w      = (const float*)d_in[8];
    const float* d1b      = (const float*)d_in[9];
    const float* rw1      = (const float*)d_in[10];
    const float* root1    = (const float*)d_in[11];
    const float* rb1      = (const float*)d_in[12];
    const float* rw2      = (const float*)d_in[13];
    const float* root2    = (const float*)d_in[14];
    const float* rb2      = (const float*)d_in[15];
    const float* dw       = (const float*)d_in[16];
    const float* db       = (const float*)d_in[17];
    float* out = (float*)d_out;

    const int* src = ei;
    const int* dst = ei + EE;

    void *p_w1, *p_xw1, *p_w2, *p_xw2, *p_z1;
    cudaGetSymbolAddress(&p_w1, g_w1);
    cudaGetSymbolAddress(&p_xw1, g_xw1);
    cudaGetSymbolAddress(&p_w2, g_w2);
    cudaGetSymbolAddress(&p_xw2, g_xw2);
    cudaGetSymbolAddress(&p_z1, g_z1);

    cudaStream_t s2 = g_fork.s2;
    cudaStream_t s3 = g_fork.s3;

    cudaEventRecord(g_fork.evStart, 0);
    cudaStreamWaitEvent(s2, g_fork.evStart, 0);
    cudaStreamWaitEvent(s3, g_fork.evStart, 0);

    // s2: init + CSR build (off the critical path)
    k_init<<<(NN + 255) / 256, 256, 0, s2>>>();
    k_count<<<EE / 256, 256, 0, s2>>>(dst);
    k_scan1<<<NBLK, 1024, 0, s2>>>();
    k_scan2<<<1, 128, 0, s2>>>();
    k_scan3<<<NBLK, 1024, 0, s2>>>();
    k_scatter<<<EE / 256, 256, 0, s2>>>(src, dst, et);
    cudaEventRecord(g_fork.evCSR, s2);

    // s3: GAT transform (+att dots), then fused GAT after CSR ready
    k_gemm_h<<<(NN + 47) / 48, 96, 0, s3>>>(x, gat_w, att_src, att_dst);
    cudaStreamWaitEvent(s3, g_fork.evCSR, 0);
    k_gat<<<NN / 8, 256, 0, s3>>>(gat_bias, d1w, d1b, batch);
    cudaEventRecord(g_fork.evGat, s3);

    // main: pack + xw1 GEMM immediately (overlaps CSR + gemm_h)
    k_pack<<<(64 * 288 + 32 * 144 + 255) / 256, 256>>>(rw1, root1, rw2, root2);
    k_gemm<64, 288, 96, 96, 8, 8><<<dim3((NN + 95) / 96, 3), 144>>>(x, (const float*)p_w1, (__half*)p_xw1, 0);
    cudaStreamWaitEvent(0, g_fork.evCSR, 0);

    // pipelined rgcn1 / xw2 halves: [0, SPLIT) then [SPLIT, NN)
    k_rgcn1<<<SPLIT / 8, 256>>>(rb1, 0);
    cudaEventRecord(g_fork.evR1, 0);
    k_rgcn1<<<(NN - SPLIT) / 8, 256>>>(rb1, SPLIT);

    // s2: xw2 for the first half while main does rgcn1_hi
    cudaStreamWaitEvent(s2, g_fork.evR1, 0);
    k_gemm<32, 144, 144, 64, 8, 8><<<dim3(SPLIT / 64, 1), 144, 0, s2>>>(
        (const float*)p_z1, (const float*)p_w2, (__half*)p_xw2, 0);
    cudaEventRecord(g_fork.evX2lo, s2);

    // main: xw2 for the second half, then join and rgcn2
    k_gemm<32, 144, 144, 64, 8, 8><<<dim3((NN - SPLIT + 63) / 64, 1), 144>>>(
        (const float*)p_z1, (const float*)p_w2, (__half*)p_xw2, SPLIT);
    cudaStreamWaitEvent(0, g_fork.evX2lo, 0);
    k_rgcn2<<<NN / 8, 256>>>(rb2, batch);

    // join GAT branch
    cudaStreamWaitEvent(0, g_fork.evGat, 0);
    k_final<<<1, 256>>>(dw, db, out);
}